// round 16
// baseline (speedup 1.0000x reference)
#include <cuda_runtime.h>
#include <cuda_fp16.h>
#include <cstdint>

#define BATCH     4
#define NHEAD     16
#define SEQ       2048
#define DHEAD     64
#define ROWSTRIDE 3072
#define NSTATE    1024
#define BM        128
#define BN        64
#define NTHREADS  128
#define KPAD      72

// scale * log2(e), folded into Q
#define SCALE_LOG2E 0.18033688011112042f

// fp16 K/V scratch: [B][H][S][D], D contiguous
__device__ __half KC[BATCH * NHEAD * SEQ * DHEAD];
__device__ __half VC[BATCH * NHEAD * SEQ * DHEAD];

__device__ __forceinline__ float ex2f(float x) {
    float y;
    asm("ex2.approx.f32 %0, %1;" : "=f"(y) : "f"(x));
    return y;
}

__device__ __forceinline__ uint32_t h2bits(__half2 h) { return *reinterpret_cast<uint32_t*>(&h); }

__device__ __forceinline__ void mma16816(float* c, const uint32_t* a, uint32_t b0, uint32_t b1) {
    asm volatile(
        "mma.sync.aligned.m16n8k16.row.col.f32.f16.f16.f32 "
        "{%0,%1,%2,%3}, {%4,%5,%6,%7}, {%8,%9}, {%0,%1,%2,%3};"
        : "+f"(c[0]), "+f"(c[1]), "+f"(c[2]), "+f"(c[3])
        : "r"(a[0]), "r"(a[1]), "r"(a[2]), "r"(a[3]), "r"(b0), "r"(b1));
}

__device__ __forceinline__ void ldsm_x4(uint32_t& r0, uint32_t& r1, uint32_t& r2, uint32_t& r3,
                                        uint32_t addr) {
    asm volatile("ldmatrix.sync.aligned.m8n8.x4.shared.b16 {%0,%1,%2,%3}, [%4];"
                 : "=r"(r0), "=r"(r1), "=r"(r2), "=r"(r3) : "r"(addr));
}

__device__ __forceinline__ void ldsm_x4_t(uint32_t& r0, uint32_t& r1, uint32_t& r2, uint32_t& r3,
                                          uint32_t addr) {
    asm volatile("ldmatrix.sync.aligned.m8n8.x4.trans.shared.b16 {%0,%1,%2,%3}, [%4];"
                 : "=r"(r0), "=r"(r1), "=r"(r2), "=r"(r3) : "r"(addr));
}

#define CP_ASYNC16(dst, src) \
    asm volatile("cp.async.ca.shared.global [%0], [%1], 16;" :: "r"(dst), "l"(src))
#define CP_COMMIT() asm volatile("cp.async.commit_group;" ::: "memory")
#define CP_WAIT(n)  asm volatile("cp.async.wait_group %0;" :: "n"(n) : "memory")

// ---------------- pre-conversion: x(K,V fp32) -> KC/VC fp16 ----------------
__global__ __launch_bounds__(256)
void conv_kernel(const float* __restrict__ x) {
    const int bs = blockIdx.x;
    const int b  = bs >> 11;
    const int s  = bs & 2047;
    const float* px = x + (size_t)bs * ROWSTRIDE;
    uint32_t* kc = reinterpret_cast<uint32_t*>(KC);
    uint32_t* vc = reinterpret_cast<uint32_t*>(VC);
#pragma unroll
    for (int it = 0; it < 2; it++) {
        const int p  = it * 256 + threadIdx.x;   // pair index [0,512)
        const int hh = p >> 5;
        const int dp = p & 31;
        float2 kf = *reinterpret_cast<const float2*>(px + NSTATE + hh * 64 + dp * 2);
        float2 vf = *reinterpret_cast<const float2*>(px + 2 * NSTATE + hh * 64 + dp * 2);
        const size_t o = ((size_t)(b * NHEAD + hh) * SEQ + s) * 32 + dp;
        kc[o] = h2bits(__floats2half2_rn(kf.x, kf.y));
        vc[o] = h2bits(__floats2half2_rn(vf.x, vf.y));
    }
}

// ---------------- attention kernel: BM=128, 4 warps, M=32/warp ----------------
__global__ __launch_bounds__(NTHREADS, 2)
void fa_kernel(const float* __restrict__ x, float* __restrict__ out) {
    __shared__ alignas(16) __half KB[2][BN][KPAD];
    __shared__ alignas(16) __half VB[2][BN][KPAD];

    const int qtile = blockIdx.x;
    const int h     = blockIdx.y;
    const int b     = blockIdx.z;
    const int tid   = threadIdx.x;
    const int lane  = tid & 31;
    const int warp  = tid >> 5;
    const int g     = lane >> 2;
    const int qr    = lane & 3;

    const size_t base  = (size_t)b * SEQ * ROWSTRIDE + (size_t)h * DHEAD;
    const size_t kvrow = (size_t)(b * NHEAD + h) * SEQ;
    const int rowA = qtile * BM + warp * 32 + g;          // mt adds mt*16 (+8 second mma row)
    const int wmax = qtile * BM + warp * 32 + 31;         // warp's max query row

    const int r8 = lane & 7;
    const int krow = (((lane >> 4) & 1) << 3) + r8;
    const int kcol = ((lane >> 3) & 1) << 3;
    const int vrow = (((lane >> 3) & 1) << 3) + r8;
    const int vcol = ((lane >> 4) & 1) << 3;

    const uint32_t aK0 = (uint32_t)__cvta_generic_to_shared(&KB[0][krow][kcol]);
    const uint32_t aV0 = (uint32_t)__cvta_generic_to_shared(&VB[0][vrow][vcol]);
    const uint32_t bufStride = (uint32_t)(BN * KPAD * 2);

    int lr[4], lc[4];
#pragma unroll
    for (int i = 0; i < 4; i++) {
        const int fi = i * NTHREADS + tid;
        lr[i] = fi >> 3;
        lc[i] = (fi & 7) << 3;
    }

    // ---- Q fragments for both M-tiles (pre-scaled, single fp16 term) ----
    uint32_t qh[2][4][4];
#pragma unroll
    for (int mt = 0; mt < 2; mt++) {
        const int r0 = rowA + mt * 16;
#pragma unroll
        for (int ks = 0; ks < 4; ks++) {
            const int c = ks * 16 + qr * 2;
            const float* p0 = x + base + (size_t)r0 * ROWSTRIDE + c;
            const float* p1 = x + base + (size_t)(r0 + 8) * ROWSTRIDE + c;
            float2 f0 = *reinterpret_cast<const float2*>(p0);
            float2 f1 = *reinterpret_cast<const float2*>(p1);
            float2 f2 = *reinterpret_cast<const float2*>(p0 + 8);
            float2 f3 = *reinterpret_cast<const float2*>(p1 + 8);
            qh[mt][ks][0] = h2bits(__floats2half2_rn(f0.x * SCALE_LOG2E, f0.y * SCALE_LOG2E));
            qh[mt][ks][1] = h2bits(__floats2half2_rn(f1.x * SCALE_LOG2E, f1.y * SCALE_LOG2E));
            qh[mt][ks][2] = h2bits(__floats2half2_rn(f2.x * SCALE_LOG2E, f2.y * SCALE_LOG2E));
            qh[mt][ks][3] = h2bits(__floats2half2_rn(f3.x * SCALE_LOG2E, f3.y * SCALE_LOG2E));
        }
    }

    float o[2][8][4];
#pragma unroll
    for (int mt = 0; mt < 2; mt++)
#pragma unroll
        for (int nd = 0; nd < 8; nd++)
#pragma unroll
            for (int e = 0; e < 4; e++) o[mt][nd][e] = 0.f;

    float m[2]  = {-INFINITY, -INFINITY};   // shared max per row pair (exact)
    float l0[2] = {0.f, 0.f};
    float l1[2] = {0.f, 0.f};

    const int njt = 2 * qtile + 2;

    // ---- prologue: async-load tile 0 ----
#pragma unroll
    for (int i = 0; i < 4; i++) {
        const __half* ksrc = KC + (kvrow + lr[i]) * DHEAD + lc[i];
        const __half* vsrc = VC + (kvrow + lr[i]) * DHEAD + lc[i];
        CP_ASYNC16((uint32_t)__cvta_generic_to_shared(&KB[0][lr[i]][lc[i]]), ksrc);
        CP_ASYNC16((uint32_t)__cvta_generic_to_shared(&VB[0][lr[i]][lc[i]]), vsrc);
    }
    CP_COMMIT();

    for (int j = 0; j < njt; j++) {
        const int buf = j & 1;
        const uint32_t bob = (uint32_t)buf * bufStride;
        const int kb = j * BN;

        if (j + 1 < njt) {
            const int kb2 = (j + 1) * BN;
            const int nb = buf ^ 1;
#pragma unroll
            for (int i = 0; i < 4; i++) {
                const __half* ksrc = KC + (kvrow + kb2 + lr[i]) * DHEAD + lc[i];
                const __half* vsrc = VC + (kvrow + kb2 + lr[i]) * DHEAD + lc[i];
                CP_ASYNC16((uint32_t)__cvta_generic_to_shared(&KB[nb][lr[i]][lc[i]]), ksrc);
                CP_ASYNC16((uint32_t)__cvta_generic_to_shared(&VB[nb][lr[i]][lc[i]]), vsrc);
            }
            CP_COMMIT();
            CP_WAIT(1);
        } else {
            CP_WAIT(0);
        }
        __syncthreads();

        // per-warp skip: tile entirely above this warp's rows contributes zero
        if (kb <= wmax) {
            // ---- S = Q K^T: one ldsm.x4 feeds 4 MMAs (2 M-tiles x 2 N-halves) ----
            float s[2][8][4];
#pragma unroll
            for (int mt = 0; mt < 2; mt++)
#pragma unroll
                for (int nt = 0; nt < 8; nt++)
#pragma unroll
                    for (int e = 0; e < 4; e++) s[mt][nt][e] = 0.f;

#pragma unroll
            for (int ks = 0; ks < 4; ks++) {
#pragma unroll
                for (int ntp = 0; ntp < 4; ntp++) {
                    const int nt = ntp * 2;
                    const uint32_t off = bob + (uint32_t)((nt * 8 * KPAD + ks * 16) * 2);
                    uint32_t bh0, bh1, bh2, bh3;
                    ldsm_x4(bh0, bh1, bh2, bh3, aK0 + off);
                    mma16816(s[0][nt],     qh[0][ks], bh0, bh1);
                    mma16816(s[0][nt + 1], qh[0][ks], bh2, bh3);
                    mma16816(s[1][nt],     qh[1][ks], bh0, bh1);
                    mma16816(s[1][nt + 1], qh[1][ks], bh2, bh3);
                }
            }

            // ---- mask + online softmax per M-tile ----
#pragma unroll
            for (int mt = 0; mt < 2; mt++) {
                const int tmin = qtile * BM + warp * 32 + mt * 16;
                const int gq0 = tmin + g;
                const int gq1 = gq0 + 8;
                if (kb + BN - 1 > tmin) {
#pragma unroll
                    for (int nt = 0; nt < 8; nt++) {
                        const int kg = kb + nt * 8 + qr * 2;
                        if (kg     > gq0) s[mt][nt][0] = -1e30f;
                        if (kg + 1 > gq0) s[mt][nt][1] = -1e30f;
                        if (kg     > gq1) s[mt][nt][2] = -1e30f;
                        if (kg + 1 > gq1) s[mt][nt][3] = -1e30f;
                    }
                }

                float mx = -INFINITY;
#pragma unroll
                for (int nt = 0; nt < 8; nt++) {
                    mx = fmaxf(mx, fmaxf(s[mt][nt][0], s[mt][nt][1]));
                    mx = fmaxf(mx, fmaxf(s[mt][nt][2], s[mt][nt][3]));
                }
                mx = fmaxf(mx, __shfl_xor_sync(0xffffffffu, mx, 1));
                mx = fmaxf(mx, __shfl_xor_sync(0xffffffffu, mx, 2));

                const float mn = fmaxf(m[mt], mx);
                const float a  = ex2f(m[mt] - mn);
                m[mt] = mn;

                float sum0 = 0.f, sum1 = 0.f;
#pragma unroll
                for (int nt = 0; nt < 8; nt++) {
                    s[mt][nt][0] = ex2f(s[mt][nt][0] - mn); sum0 += s[mt][nt][0];
                    s[mt][nt][1] = ex2f(s[mt][nt][1] - mn); sum0 += s[mt][nt][1];
                    s[mt][nt][2] = ex2f(s[mt][nt][2] - mn); sum1 += s[mt][nt][2];
                    s[mt][nt][3] = ex2f(s[mt][nt][3] - mn); sum1 += s[mt][nt][3];
                }
                sum0 += __shfl_xor_sync(0xffffffffu, sum0, 1);
                sum0 += __shfl_xor_sync(0xffffffffu, sum0, 2);
                sum1 += __shfl_xor_sync(0xffffffffu, sum1, 1);
                sum1 += __shfl_xor_sync(0xffffffffu, sum1, 2);
                l0[mt] = l0[mt] * a + sum0;
                l1[mt] = l1[mt] * a + sum1;

#pragma unroll
                for (int nd = 0; nd < 8; nd++) {
                    o[mt][nd][0] *= a; o[mt][nd][1] *= a;
                    o[mt][nd][2] *= a; o[mt][nd][3] *= a;
                }
            }

            // ---- O += P V: one ldsm.x4.trans feeds 4 MMAs ----
#pragma unroll
            for (int ks2 = 0; ks2 < 4; ks2++) {
                const int n2 = ks2 * 2;
                uint32_t pa0[4], pa1[4];
                pa0[0] = h2bits(__floats2half2_rn(s[0][n2][0],     s[0][n2][1]));
                pa0[1] = h2bits(__floats2half2_rn(s[0][n2][2],     s[0][n2][3]));
                pa0[2] = h2bits(__floats2half2_rn(s[0][n2 + 1][0], s[0][n2 + 1][1]));
                pa0[3] = h2bits(__floats2half2_rn(s[0][n2 + 1][2], s[0][n2 + 1][3]));
                pa1[0] = h2bits(__floats2half2_rn(s[1][n2][0],     s[1][n2][1]));
                pa1[1] = h2bits(__floats2half2_rn(s[1][n2][2],     s[1][n2][3]));
                pa1[2] = h2bits(__floats2half2_rn(s[1][n2 + 1][0], s[1][n2 + 1][1]));
                pa1[3] = h2bits(__floats2half2_rn(s[1][n2 + 1][2], s[1][n2 + 1][3]));
#pragma unroll
                for (int ndp = 0; ndp < 4; ndp++) {
                    const int nd = ndp * 2;
                    const uint32_t off = bob + (uint32_t)((ks2 * 16 * KPAD + nd * 8) * 2);
                    uint32_t bh0, bh1, bh2, bh3;
                    ldsm_x4_t(bh0, bh1, bh2, bh3, aV0 + off);
                    mma16816(o[0][nd],     pa0, bh0, bh1);
                    mma16816(o[0][nd + 1], pa0, bh2, bh3);
                    mma16816(o[1][nd],     pa1, bh0, bh1);
                    mma16816(o[1][nd + 1], pa1, bh2, bh3);
                }
            }
        }
        __syncthreads();
    }

    // ---- epilogue ----
    float* ob = out + (size_t)b * SEQ * NSTATE + (size_t)h * DHEAD;
#pragma unroll
    for (int mt = 0; mt < 2; mt++) {
        const int r0 = rowA + mt * 16;
        const float inv0 = 1.f / l0[mt];
        const float inv1 = 1.f / l1[mt];
#pragma unroll
        for (int nd = 0; nd < 8; nd++) {
            const int dcol = nd * 8 + qr * 2;
            float2 v0; v0.x = o[mt][nd][0] * inv0; v0.y = o[mt][nd][1] * inv0;
            float2 v1; v1.x = o[mt][nd][2] * inv1; v1.y = o[mt][nd][3] * inv1;
            *reinterpret_cast<float2*>(ob + (size_t)r0 * NSTATE + dcol) = v0;
            *reinterpret_cast<float2*>(ob + (size_t)(r0 + 8) * NSTATE + dcol) = v1;
        }
    }
}

extern "C" void kernel_launch(void* const* d_in, const int* in_sizes, int n_in,
                              void* d_out, int out_size) {
    const float* x = (const float*)d_in[0];
    float* out = (float*)d_out;
    conv_kernel<<<BATCH * SEQ, 256>>>(x);
    dim3 grid(SEQ / BM, NHEAD, BATCH);
    fa_kernel<<<grid, NTHREADS>>>(x, out);
}